// round 1
// baseline (speedup 1.0000x reference)
#include <cuda_runtime.h>
#include <cstdint>

// Problem constants
#define BB 128
#define TT 256
#define DD 768
#define SS 128
#define NROWS (BB*TT)   // 32768

// Scratch (allocation-free rule: __device__ globals)
__device__ float g_Bx[NROWS * SS];      // 16.8 MB
__device__ float g_states[NROWS * SS];  // 16.8 MB

// ---------------------------------------------------------------------------
// tf32 helpers
// ---------------------------------------------------------------------------
__device__ __forceinline__ uint32_t f2tf32(float f) {
    uint32_t u;
    asm("cvt.rna.tf32.f32 %0, %1;" : "=r"(u) : "f"(f));
    return u;
}
__device__ __forceinline__ float4 tf32x4(float4 v) {
    v.x = __uint_as_float(f2tf32(v.x));
    v.y = __uint_as_float(f2tf32(v.y));
    v.z = __uint_as_float(f2tf32(v.z));
    v.w = __uint_as_float(f2tf32(v.w));
    return v;
}
__device__ __forceinline__ void mma8(float* c, const uint32_t* a, const uint32_t* b) {
    asm volatile(
        "mma.sync.aligned.m16n8k8.row.col.f32.tf32.tf32.f32 "
        "{%0,%1,%2,%3}, {%4,%5,%6,%7}, {%8,%9}, {%0,%1,%2,%3};"
        : "+f"(c[0]), "+f"(c[1]), "+f"(c[2]), "+f"(c[3])
        : "r"(a[0]), "r"(a[1]), "r"(a[2]), "r"(a[3]),
          "r"(b[0]), "r"(b[1]));
}

// ---------------------------------------------------------------------------
// Generic two-segment GEMM: C[M,N] = sum_seg Aseg[M,Kseg] * Wseg[N,Kseg]^T
// Block tile 128x128, BK=16, 256 threads (8 warps as 4x2, warp tile 32x64).
// Smem pitch 20 floats: (20*m + k) mod 32 covers all banks -> conflict-free
// fragment loads. Double-buffered with register-staged global prefetch.
// ---------------------------------------------------------------------------
__global__ void __launch_bounds__(256)
gemm_tf32(const float* __restrict__ A0, int lda0,
          const float* __restrict__ W0, int ldw0, int K0,
          const float* __restrict__ A1, int lda1,
          const float* __restrict__ W1, int ldw1, int K1,
          float* __restrict__ Cp, int ldc)
{
    __shared__ float As[2][128][20];
    __shared__ float Bs[2][128][20];

    const int tid  = threadIdx.x;
    const int lane = tid & 31;
    const int wid  = tid >> 5;
    const int wm   = wid >> 1;   // 0..3
    const int wn   = wid & 1;    // 0..1
    const int rowBlock = blockIdx.y * 128;
    const int colBlock = blockIdx.x * 128;
    const int arow = tid >> 2;          // 0..63
    const int acol = (tid & 3) << 2;    // 0,4,8,12

    const int kt0 = K0 >> 4;
    const int NT  = kt0 + (K1 >> 4);

    float acc[2][8][4];
#pragma unroll
    for (int mi = 0; mi < 2; ++mi)
#pragma unroll
        for (int ni = 0; ni < 8; ++ni)
#pragma unroll
            for (int j = 0; j < 4; ++j) acc[mi][ni][j] = 0.f;

    float4 ra0, ra1, rb0, rb1;

    auto loadT = [&](int t) {
        const float* Ap; const float* Wp; int la, lw, kb;
        if (t < kt0) { Ap = A0; la = lda0; Wp = W0; lw = ldw0; kb = t << 4; }
        else         { Ap = A1; la = lda1; Wp = W1; lw = ldw1; kb = (t - kt0) << 4; }
        const float* ap = Ap + (rowBlock + arow) * la + kb + acol;
        ra0 = *(const float4*)ap;
        ra1 = *(const float4*)(ap + 64 * la);
        const float* wp = Wp + (colBlock + arow) * lw + kb + acol;
        rb0 = *(const float4*)wp;
        rb1 = *(const float4*)(wp + 64 * lw);
    };
    auto stsT = [&](int buf) {
        *(float4*)&As[buf][arow][acol]      = tf32x4(ra0);
        *(float4*)&As[buf][arow + 64][acol] = tf32x4(ra1);
        *(float4*)&Bs[buf][arow][acol]      = tf32x4(rb0);
        *(float4*)&Bs[buf][arow + 64][acol] = tf32x4(rb1);
    };

    loadT(0);
    stsT(0);
    __syncthreads();

    for (int t = 0; t < NT; ++t) {
        const int cur = t & 1;
        const bool hasNext = (t + 1) < NT;
        if (hasNext) loadT(t + 1);

#pragma unroll
        for (int kf = 0; kf < 2; ++kf) {
            const int kb = (kf << 3) + (lane & 3);
            uint32_t af[2][4];
#pragma unroll
            for (int mi = 0; mi < 2; ++mi) {
                const int r = wm * 32 + mi * 16 + (lane >> 2);
                af[mi][0] = __float_as_uint(As[cur][r][kb]);
                af[mi][1] = __float_as_uint(As[cur][r + 8][kb]);
                af[mi][2] = __float_as_uint(As[cur][r][kb + 4]);
                af[mi][3] = __float_as_uint(As[cur][r + 8][kb + 4]);
            }
            uint32_t bf[8][2];
#pragma unroll
            for (int ni = 0; ni < 8; ++ni) {
                const int c = wn * 64 + ni * 8 + (lane >> 2);
                bf[ni][0] = __float_as_uint(Bs[cur][c][kb]);
                bf[ni][1] = __float_as_uint(Bs[cur][c][kb + 4]);
            }
#pragma unroll
            for (int mi = 0; mi < 2; ++mi)
#pragma unroll
                for (int ni = 0; ni < 8; ++ni)
                    mma8(acc[mi][ni], af[mi], bf[ni]);
        }

        if (hasNext) stsT(cur ^ 1);
        __syncthreads();
    }

    // Epilogue: c0,c1 -> (r, c), (r, c+1); c2,c3 -> (r+8, c), (r+8, c+1)
#pragma unroll
    for (int mi = 0; mi < 2; ++mi) {
#pragma unroll
        for (int ni = 0; ni < 8; ++ni) {
            const int r = rowBlock + wm * 32 + mi * 16 + (lane >> 2);
            const int c = colBlock + wn * 64 + ni * 8 + 2 * (lane & 3);
            *(float2*)&Cp[r * ldc + c]       = make_float2(acc[mi][ni][0], acc[mi][ni][1]);
            *(float2*)&Cp[(r + 8) * ldc + c] = make_float2(acc[mi][ni][2], acc[mi][ni][3]);
        }
    }
}

// ---------------------------------------------------------------------------
// Sequential scan: one block per batch b. 512 threads = (s in [0,128)) x
// (q in [0,4)) K-quarters. A rows live in registers; state broadcast from smem.
// st_new[s] = clip( sum_k A[s][k]*st[k] + Bx[b,t,s] )
// ---------------------------------------------------------------------------
__global__ void __launch_bounds__(512)
scan_kernel(const float* __restrict__ A)
{
    __shared__ float st[SS];
    __shared__ float part[4][SS];

    const int tid = threadIdx.x;
    const int s = tid & 127;
    const int q = tid >> 7;

    float a[32];
    const float4* arp = (const float4*)(A + s * SS + q * 32);
#pragma unroll
    for (int j = 0; j < 8; ++j) {
        float4 v = arp[j];
        a[4 * j]     = v.x; a[4 * j + 1] = v.y;
        a[4 * j + 2] = v.z; a[4 * j + 3] = v.w;
    }

    if (tid < SS) st[tid] = 0.f;

    const int b = blockIdx.x;
    const float* bx = g_Bx + (size_t)b * TT * SS;
    float* so = g_states + (size_t)b * TT * SS;

    float bxv = (q == 0) ? bx[s] : 0.f;
    __syncthreads();

    for (int t = 0; t < TT; ++t) {
        float p = 0.f;
        const float4* stv = (const float4*)(st + q * 32);
#pragma unroll
        for (int j = 0; j < 8; ++j) {
            float4 v = stv[j];
            p = fmaf(a[4 * j],     v.x, p);
            p = fmaf(a[4 * j + 1], v.y, p);
            p = fmaf(a[4 * j + 2], v.z, p);
            p = fmaf(a[4 * j + 3], v.w, p);
        }
        part[q][s] = p;
        __syncthreads();
        if (q == 0) {
            float v = part[0][s] + part[1][s] + part[2][s] + part[3][s] + bxv;
            v = fminf(fmaxf(v, -10.f), 10.f);
            st[s] = v;
            so[t * SS + s] = v;
            if (t + 1 < TT) bxv = bx[(t + 1) * SS + s];
        }
        __syncthreads();
    }
}

// ---------------------------------------------------------------------------
// Fused gate + residual mix + LayerNorm. One block (128 threads) per row.
// io holds the pre-gate GEMM output on entry; final result on exit.
// ---------------------------------------------------------------------------
__global__ void __launch_bounds__(128)
mix_ln_kernel(const float* __restrict__ x,
              const float* __restrict__ gate_w,
              const float* __restrict__ gate_b,
              const float* __restrict__ gamma,
              const float* __restrict__ beta,
              float* __restrict__ io)
{
    __shared__ float red[4][2];

    const int row = blockIdx.x;
    const int tid = threadIdx.x;
    const int lane = tid & 31, w = tid >> 5;
    const float* xr = x + (size_t)row * DD;
    float* tr = io + (size_t)row * DD;

    float xs[6], ts[6];
    float l0 = 0.f, l1 = 0.f;
#pragma unroll
    for (int k = 0; k < 6; ++k) {
        const int i = tid + k * 128;
        xs[k] = xr[i];
        ts[k] = tr[i];
        l0 = fmaf(xs[k], gate_w[i], l0);
        l1 = fmaf(xs[k], gate_w[DD + i], l1);
    }
#pragma unroll
    for (int o = 16; o; o >>= 1) {
        l0 += __shfl_xor_sync(0xffffffffu, l0, o);
        l1 += __shfl_xor_sync(0xffffffffu, l1, o);
    }
    if (lane == 0) { red[w][0] = l0; red[w][1] = l1; }
    __syncthreads();
    l0 = red[0][0] + red[1][0] + red[2][0] + red[3][0] + gate_b[0];
    l1 = red[0][1] + red[1][1] + red[2][1] + red[3][1] + gate_b[1];

    const float mx = fmaxf(l0, l1);
    const float e0 = expf(l0 - mx), e1 = expf(l1 - mx);
    const float inv = 1.f / (e0 + e1);
    const float g0 = e0 * inv, g1 = e1 * inv;

    float mix[6];
    float s = 0.f, s2 = 0.f;
#pragma unroll
    for (int k = 0; k < 6; ++k) {
        mix[k] = g0 * ts[k] + g1 * xs[k];
        s += mix[k];
        s2 = fmaf(mix[k], mix[k], s2);
    }
    __syncthreads();  // before reusing red
#pragma unroll
    for (int o = 16; o; o >>= 1) {
        s  += __shfl_xor_sync(0xffffffffu, s, o);
        s2 += __shfl_xor_sync(0xffffffffu, s2, o);
    }
    if (lane == 0) { red[w][0] = s; red[w][1] = s2; }
    __syncthreads();
    s  = red[0][0] + red[1][0] + red[2][0] + red[3][0];
    s2 = red[0][1] + red[1][1] + red[2][1] + red[3][1];

    const float mu = s * (1.f / DD);
    float var = s2 * (1.f / DD) - mu * mu;
    var = fmaxf(var, 0.f);
    const float rstd = rsqrtf(var + 1e-5f);

#pragma unroll
    for (int k = 0; k < 6; ++k) {
        const int i = tid + k * 128;
        tr[i] = (mix[k] - mu) * rstd * gamma[i] + beta[i];
    }
}

// ---------------------------------------------------------------------------
// Launch
// ---------------------------------------------------------------------------
extern "C" void kernel_launch(void* const* d_in, const int* in_sizes, int n_in,
                              void* d_out, int out_size)
{
    const float* x      = (const float*)d_in[0];
    const float* A      = (const float*)d_in[1];
    const float* B_w    = (const float*)d_in[2];
    const float* C_w    = (const float*)d_in[3];
    const float* D_w    = (const float*)d_in[4];
    const float* gate_w = (const float*)d_in[5];
    const float* gate_b = (const float*)d_in[6];
    const float* gamma  = (const float*)d_in[7];
    const float* beta   = (const float*)d_in[8];
    float* out = (float*)d_out;

    float *Bx = nullptr, *St = nullptr;
    cudaGetSymbolAddress((void**)&Bx, g_Bx);
    cudaGetSymbolAddress((void**)&St, g_states);

    // 1) Bx = x @ B_w^T   [32768 x 128], K = 768 (single segment)
    gemm_tf32<<<dim3(1, NROWS / 128), 256>>>(
        x, DD, B_w, DD, DD,
        x, DD, B_w, DD, 0,
        Bx, SS);

    // 2) sequential scan -> states
    scan_kernel<<<BB, 512>>>(A);

    // 3) out_tmp = states @ C_w^T + x @ D_w^T   [32768 x 768], K = 128 + 768
    gemm_tf32<<<dim3(DD / 128, NROWS / 128), 256>>>(
        St, SS, C_w, SS, SS,
        x, DD, D_w, DD, DD,
        out, DD);

    // 4) gate + residual mix + LayerNorm (in place on d_out)
    mix_ln_kernel<<<NROWS, 128>>>(x, gate_w, gate_b, gamma, beta, out);
}